// round 4
// baseline (speedup 1.0000x reference)
#include <cuda_runtime.h>
#include <math.h>

// Problem dims (fixed by the reference setup_inputs)
#define BB   2
#define NN   1024
#define HG   64            // H*G
#define NBATCH (BB*HG)     // 128 independent GEMM batches
#define NROWS  (BB*NN*HG)  // 131072 SH rows per side
#define DPAD 16            // 15 SH components padded to 16 for float4

// Scratch: Y_q / Y_k in [B, H, G, N, 16] layout (batch-major, row n, padded d)
__device__ float g_Yq[(size_t)NBATCH * NN * DPAD];
__device__ float g_Yk[(size_t)NBATCH * NN * DPAD];

// ---------------------------------------------------------------------------
// packed f32x2 helpers (Blackwell FFMA2 — only reachable via PTX)
// ---------------------------------------------------------------------------
__device__ __forceinline__ void fma2(unsigned long long& d,
                                     unsigned long long a,
                                     unsigned long long b)
{
    asm("fma.rn.f32x2 %0, %1, %2, %0;" : "+l"(d) : "l"(a), "l"(b));
}

__device__ __forceinline__ float2 unpack2(unsigned long long v)
{
    float2 r;
    asm("mov.b64 {%0, %1}, %2;" : "=f"(r.x), "=f"(r.y) : "l"(v));
    return r;
}

// ---------------------------------------------------------------------------
// Kernel 1: rotate -> normalize -> spherical harmonics for BOTH q and k.
// One thread per (side, b, n, h, g). 1/sqrt(15) folded into the q side.
// ---------------------------------------------------------------------------
__global__ void sh_expand_kernel(const float* __restrict__ q_in,
                                 const float* __restrict__ k_in,
                                 const float* __restrict__ rq_in,
                                 const float* __restrict__ rk_in)
{
    int gt = blockIdx.x * blockDim.x + threadIdx.x;
    if (gt >= 2 * NROWS) return;
    int which = gt >= NROWS;          // 0 -> q, 1 -> k
    int t = gt - which * NROWS;

    const float* v_in = which ? k_in : q_in;
    const float* r_in = which ? rk_in : rq_in;
    float scale = which ? 1.0f : 0.2581988897471611f;  // 1/sqrt(15)

    int hg = t & (HG - 1);       // h*G + g
    int bn = t >> 6;             // b*N + n
    int b  = bn >> 10;           // /N
    int n  = bn & (NN - 1);

    const float* q = v_in + (size_t)t * 3;
    const float* r = r_in + (size_t)bn * 9;
    float q0 = q[0], q1 = q[1], q2 = q[2];

    float vx = r[0]*q0 + r[1]*q1 + r[2]*q2;
    float vy = r[3]*q0 + r[4]*q1 + r[5]*q2;
    float vz = r[6]*q0 + r[7]*q1 + r[8]*q2;

    float nrm = sqrtf(vx*vx + vy*vy + vz*vz);
    float inv = 1.0f / fmaxf(nrm, 1e-12f);
    float x = vx*inv, y = vy*inv, z = vz*inv;
    float x2 = x*x, y2 = y*y, z2 = z*z;

    const float f1 = 0.4886025119029199f * scale;  // sqrt(3/(4pi))
    const float f2 = 0.6307831305050401f * scale;  // sqrt(5/(4pi))
    const float f3 = 0.7463526651802308f * scale;  // sqrt(7/(4pi))
    const float s3  = 1.7320508075688772f;
    const float s15 = 3.8729833462074170f;
    const float c1  = 0.6123724356957945f;         // sqrt(3/8)
    const float c3  = 0.7905694150420949f;         // sqrt(5/8)

    float Y0  = f1 * x;
    float Y1  = f1 * y;
    float Y2  = f1 * z;

    float Y3  = f2 * (s3 * x * z);
    float Y4  = f2 * (s3 * x * y);
    float Y5  = f2 * (y2 - 0.5f * (x2 + z2));
    float Y6  = f2 * (s3 * y * z);
    float Y7  = f2 * (0.5f * s3) * (z2 - x2);

    float Y8  = f3 * (c3 * x * (3.0f * z2 - x2));
    float Y9  = f3 * (s15 * x * y * z);
    float Y10 = f3 * (c1 * x * (4.0f * y2 - x2 - z2));
    float Y11 = f3 * (0.5f * y * (2.0f * y2 - 3.0f * x2 - 3.0f * z2));
    float Y12 = f3 * (c1 * z * (4.0f * y2 - x2 - z2));
    float Y13 = f3 * (0.5f * s15) * (y * (z2 - x2));
    float Y14 = f3 * (c3 * z * (z2 - 3.0f * x2));

    float* Y = which ? g_Yk : g_Yq;
    size_t obase = (((size_t)b * HG + hg) * NN + n) * DPAD;
    float4* o = (float4*)(Y + obase);
    o[0] = make_float4(Y0,  Y1,  Y2,  Y3);
    o[1] = make_float4(Y4,  Y5,  Y6,  Y7);
    o[2] = make_float4(Y8,  Y9,  Y10, Y11);
    o[3] = make_float4(Y12, Y13, Y14, 0.0f);
}

// ---------------------------------------------------------------------------
// Kernel 2: batched small-K GEMM with packed f32x2 FMA.
// scores[batch, n, m] = sum_d Yq[n,d] * Yk[m,d]
// 64x128 output tile per block, 256 threads, 4x8 micro-tile per thread
// (4 rows, cols split ma / 64+ma so lane accesses are 16B-strided:
// conflict-free LDS, coalesced STG).
// Per k per thread: 2 LDS.128 for duplicated-A pairs (warp-broadcast),
// 2 LDS.128 for B pairs, 16 FFMA2. Small footprint -> 3 CTAs/SM.
// ---------------------------------------------------------------------------
__global__ void __launch_bounds__(256, 3) score_gemm_kernel(float* __restrict__ out)
{
    __shared__ __align__(16) float2 AsD[15][64];   // [k][n] duplicated pairs
    __shared__ __align__(16) float  Bs[15][128];   // [k][m]

    int batch = blockIdx.z;
    int n0 = blockIdx.y * 64;
    int m0 = blockIdx.x * 128;
    int tid = threadIdx.x;

    // ---- stage tiles (A: 1 float4/thread, B: 2 float4/thread, coalesced) ----
    const float4* A4 = (const float4*)(g_Yq + (size_t)batch * NN * DPAD);
    const float4* B4 = (const float4*)(g_Yk + (size_t)batch * NN * DPAD);
    {
        int row = tid >> 2;             // 0..63
        int c   = tid & 3;              // k-chunk
        float4 va = A4[(size_t)(n0 + row) * 4 + c];
        int kb = c * 4;
        AsD[kb + 0][row] = make_float2(va.x, va.x);
        AsD[kb + 1][row] = make_float2(va.y, va.y);
        AsD[kb + 2][row] = make_float2(va.z, va.z);
        if (kb + 3 < 15) AsD[kb + 3][row] = make_float2(va.w, va.w);
    }
    #pragma unroll
    for (int i = 0; i < 2; i++) {
        int idx = tid + i * 256;        // 0..511
        int row = idx >> 2;             // 0..127
        int c   = idx & 3;
        float4 vb = B4[(size_t)(m0 + row) * 4 + c];
        int kb = c * 4;
        Bs[kb + 0][row] = vb.x;
        Bs[kb + 1][row] = vb.y;
        Bs[kb + 2][row] = vb.z;
        if (kb + 3 < 15) Bs[kb + 3][row] = vb.w;
    }
    __syncthreads();

    int tx = tid & 15;           // m micro-tile
    int ty = tid >> 4;           // n micro-tile (0..15)
    int na = ty * 4;             // rows na..na+3
    int ma = tx * 4;             // cols ma..ma+3 and 64+ma..64+ma+3

    // acc[r][p]: r = row na+r; p = col pair (0,1 -> ma+{0,1},{2,3};
    //                                        2,3 -> 64+ma+{0,1},{2,3})
    unsigned long long acc[4][4];
    #pragma unroll
    for (int r = 0; r < 4; r++)
        #pragma unroll
        for (int p = 0; p < 4; p++) acc[r][p] = 0ull;

    #pragma unroll
    for (int k = 0; k < 15; k++) {
        // a: duplicated pairs, 2x LDS.128 (broadcast within warp)
        ulonglong2 a01 = *(const ulonglong2*)&AsD[k][na + 0];  // rows na+0,1
        ulonglong2 a23 = *(const ulonglong2*)&AsD[k][na + 2];  // rows na+2,3
        // b: natural pairs, 2x LDS.128 (16B lane stride, conflict-free)
        ulonglong2 bA = *(const ulonglong2*)&Bs[k][ma];        // {b0,b1},{b2,b3}
        ulonglong2 bB = *(const ulonglong2*)&Bs[k][64 + ma];

        fma2(acc[0][0], a01.x, bA.x); fma2(acc[0][1], a01.x, bA.y);
        fma2(acc[0][2], a01.x, bB.x); fma2(acc[0][3], a01.x, bB.y);
        fma2(acc[1][0], a01.y, bA.x); fma2(acc[1][1], a01.y, bA.y);
        fma2(acc[1][2], a01.y, bB.x); fma2(acc[1][3], a01.y, bB.y);
        fma2(acc[2][0], a23.x, bA.x); fma2(acc[2][1], a23.x, bA.y);
        fma2(acc[2][2], a23.x, bB.x); fma2(acc[2][3], a23.x, bB.y);
        fma2(acc[3][0], a23.y, bA.x); fma2(acc[3][1], a23.y, bA.y);
        fma2(acc[3][2], a23.y, bB.x); fma2(acc[3][3], a23.y, bB.y);
    }

    // ---- store: two coalesced float4 per row, 4 rows ----
    float* o = out + (size_t)batch * NN * NN + (size_t)n0 * NN + m0;
    #pragma unroll
    for (int r = 0; r < 4; r++) {
        float2 l0 = unpack2(acc[r][0]);
        float2 l1 = unpack2(acc[r][1]);
        float2 l2 = unpack2(acc[r][2]);
        float2 l3 = unpack2(acc[r][3]);
        float* orow = o + (size_t)(na + r) * NN;
        __stcs((float4*)(orow + ma),      make_float4(l0.x, l0.y, l1.x, l1.y));
        __stcs((float4*)(orow + 64 + ma), make_float4(l2.x, l2.y, l3.x, l3.y));
    }
}

// ---------------------------------------------------------------------------
extern "C" void kernel_launch(void* const* d_in, const int* in_sizes, int n_in,
                              void* d_out, int out_size)
{
    const float* q  = (const float*)d_in[0];
    const float* k  = (const float*)d_in[1];
    const float* rq = (const float*)d_in[2];
    const float* rk = (const float*)d_in[3];
    float* out = (float*)d_out;

    int blocks = (2 * NROWS + 255) / 256;
    sh_expand_kernel<<<blocks, 256>>>(q, k, rq, rk);

    dim3 grid(NN / 128, NN / 64, NBATCH);  // 8 x 16 x 128
    score_gemm_kernel<<<grid, 256>>>(out);
}

// round 5
// speedup vs baseline: 1.1924x; 1.1924x over previous
#include <cuda_runtime.h>
#include <math.h>

// Problem dims (fixed by the reference setup_inputs)
#define BB   2
#define NN   1024
#define HG   64            // H*G
#define NBATCH (BB*HG)     // 128 independent GEMM batches
#define NROWS  (BB*NN*HG)  // 131072 SH rows per side
#define DPAD 16            // 15 SH components padded to 16 for float4

// Scratch: Y_q / Y_k in [B, H, G, N, 16] layout (batch-major, row n, padded d)
__device__ float g_Yq[(size_t)NBATCH * NN * DPAD];
__device__ float g_Yk[(size_t)NBATCH * NN * DPAD];

typedef unsigned long long u64;

// ---------------------------------------------------------------------------
// packed f32x2 helpers (Blackwell FFMA2 — only reachable via PTX)
// ---------------------------------------------------------------------------
__device__ __forceinline__ void fma2(u64& d, u64 a, u64 b)
{
    asm("fma.rn.f32x2 %0, %1, %2, %0;" : "+l"(d) : "l"(a), "l"(b));
}

__device__ __forceinline__ u64 pack_dup(float v)
{
    u64 r;
    asm("mov.b64 %0, {%1, %1};" : "=l"(r) : "f"(v));
    return r;
}

__device__ __forceinline__ float2 unpack2(u64 v)
{
    float2 r;
    asm("mov.b64 {%0, %1}, %2;" : "=f"(r.x), "=f"(r.y) : "l"(v));
    return r;
}

// ---------------------------------------------------------------------------
// Kernel 1: rotate -> normalize -> spherical harmonics for BOTH q and k.
// One thread per (side, b, n, h, g). 1/sqrt(15) folded into the q side.
// ---------------------------------------------------------------------------
__global__ void sh_expand_kernel(const float* __restrict__ q_in,
                                 const float* __restrict__ k_in,
                                 const float* __restrict__ rq_in,
                                 const float* __restrict__ rk_in)
{
    int gt = blockIdx.x * blockDim.x + threadIdx.x;
    if (gt >= 2 * NROWS) return;
    int which = gt >= NROWS;          // 0 -> q, 1 -> k
    int t = gt - which * NROWS;

    const float* v_in = which ? k_in : q_in;
    const float* r_in = which ? rk_in : rq_in;
    float scale = which ? 1.0f : 0.2581988897471611f;  // 1/sqrt(15)

    int hg = t & (HG - 1);       // h*G + g
    int bn = t >> 6;             // b*N + n
    int b  = bn >> 10;           // /N
    int n  = bn & (NN - 1);

    const float* q = v_in + (size_t)t * 3;
    const float* r = r_in + (size_t)bn * 9;
    float q0 = q[0], q1 = q[1], q2 = q[2];

    float vx = r[0]*q0 + r[1]*q1 + r[2]*q2;
    float vy = r[3]*q0 + r[4]*q1 + r[5]*q2;
    float vz = r[6]*q0 + r[7]*q1 + r[8]*q2;

    float nrm = sqrtf(vx*vx + vy*vy + vz*vz);
    float inv = 1.0f / fmaxf(nrm, 1e-12f);
    float x = vx*inv, y = vy*inv, z = vz*inv;
    float x2 = x*x, y2 = y*y, z2 = z*z;

    const float f1 = 0.4886025119029199f * scale;  // sqrt(3/(4pi))
    const float f2 = 0.6307831305050401f * scale;  // sqrt(5/(4pi))
    const float f3 = 0.7463526651802308f * scale;  // sqrt(7/(4pi))
    const float s3  = 1.7320508075688772f;
    const float s15 = 3.8729833462074170f;
    const float c1  = 0.6123724356957945f;         // sqrt(3/8)
    const float c3  = 0.7905694150420949f;         // sqrt(5/8)

    float Y0  = f1 * x;
    float Y1  = f1 * y;
    float Y2  = f1 * z;

    float Y3  = f2 * (s3 * x * z);
    float Y4  = f2 * (s3 * x * y);
    float Y5  = f2 * (y2 - 0.5f * (x2 + z2));
    float Y6  = f2 * (s3 * y * z);
    float Y7  = f2 * (0.5f * s3) * (z2 - x2);

    float Y8  = f3 * (c3 * x * (3.0f * z2 - x2));
    float Y9  = f3 * (s15 * x * y * z);
    float Y10 = f3 * (c1 * x * (4.0f * y2 - x2 - z2));
    float Y11 = f3 * (0.5f * y * (2.0f * y2 - 3.0f * x2 - 3.0f * z2));
    float Y12 = f3 * (c1 * z * (4.0f * y2 - x2 - z2));
    float Y13 = f3 * (0.5f * s15) * (y * (z2 - x2));
    float Y14 = f3 * (c3 * z * (z2 - 3.0f * x2));

    float* Y = which ? g_Yk : g_Yq;
    size_t obase = (((size_t)b * HG + hg) * NN + n) * DPAD;
    float4* o = (float4*)(Y + obase);
    o[0] = make_float4(Y0,  Y1,  Y2,  Y3);
    o[1] = make_float4(Y4,  Y5,  Y6,  Y7);
    o[2] = make_float4(Y8,  Y9,  Y10, Y11);
    o[3] = make_float4(Y12, Y13, Y14, 0.0f);
}

// ---------------------------------------------------------------------------
// Kernel 2: batched small-K GEMM with packed f32x2 FMA.
// scores[batch, n, m] = sum_d Yq[n,d] * Yk[m,d]
// 128x128 tile per block, 256 threads, 8x8 micro-tile per thread.
// Accumulators packed over ROW pairs: acc = {D[n][m], D[n+1][m]}.
//   A side: natural consecutive-row pairs straight from LDS.128 (no packing).
//   B side: scalar float4 from smem, duplicated to {b,b} via register MOVs.
// -> 64 lane-bytes of LDS per thread per k for 64 FMAs (1.0 B/FMA).
// Manually software-pipelined: k+1 LDS issued before k's FFMA2 block.
// ---------------------------------------------------------------------------
__global__ void __launch_bounds__(256, 2) score_gemm_kernel(float* __restrict__ out)
{
    __shared__ __align__(16) float As[15][128];   // [k][n]
    __shared__ __align__(16) float Bs[15][128];   // [k][m]

    int batch = blockIdx.z;
    int n0 = blockIdx.y * 128;
    int m0 = blockIdx.x * 128;
    int tid = threadIdx.x;

    // ---- stage tiles (each thread: 2 float4 per side, coalesced) ----
    const float4* A4 = (const float4*)(g_Yq + (size_t)batch * NN * DPAD);
    const float4* B4 = (const float4*)(g_Yk + (size_t)batch * NN * DPAD);
    #pragma unroll
    for (int i = 0; i < 2; i++) {
        int idx = tid + i * 256;        // 0..511
        int row = idx >> 2;             // 0..127
        int c   = idx & 3;              // k-chunk
        float4 va = A4[(size_t)(n0 + row) * 4 + c];
        float4 vb = B4[(size_t)(m0 + row) * 4 + c];
        int kb = c * 4;
        As[kb + 0][row] = va.x;
        As[kb + 1][row] = va.y;
        As[kb + 2][row] = va.z;
        if (kb + 3 < 15) As[kb + 3][row] = va.w;
        Bs[kb + 0][row] = vb.x;
        Bs[kb + 1][row] = vb.y;
        Bs[kb + 2][row] = vb.z;
        if (kb + 3 < 15) Bs[kb + 3][row] = vb.w;
    }
    __syncthreads();

    int tx = tid & 15;           // m micro-tile
    int ty = tid >> 4;           // n micro-tile (0..15)
    int na = ty * 8;             // rows na..na+7 (consecutive)
    int ma = tx * 4;             // cols ma..ma+3 and 64+ma..64+ma+3

    // acc[p][c]: p = row pair {na+2p, na+2p+1}; c = col (0..3 -> ma+c,
    //                                                     4..7 -> 64+ma+c-4)
    u64 acc[4][8];
    #pragma unroll
    for (int p = 0; p < 4; p++)
        #pragma unroll
        for (int c = 0; c < 8; c++) acc[p][c] = 0ull;

    // prologue: load k=0 operands
    ulonglong2 a01 = *(const ulonglong2*)&As[0][na];      // pairs rows na..na+3
    ulonglong2 a23 = *(const ulonglong2*)&As[0][na + 4];  // pairs rows na+4..na+7
    float4 fb0 = *(const float4*)&Bs[0][ma];
    float4 fb1 = *(const float4*)&Bs[0][64 + ma];

    #pragma unroll
    for (int k = 0; k < 15; k++) {
        // duplicate B scalars into {b,b} pairs (ALU pipe)
        u64 b[8];
        b[0] = pack_dup(fb0.x); b[1] = pack_dup(fb0.y);
        b[2] = pack_dup(fb0.z); b[3] = pack_dup(fb0.w);
        b[4] = pack_dup(fb1.x); b[5] = pack_dup(fb1.y);
        b[6] = pack_dup(fb1.z); b[7] = pack_dup(fb1.w);

        u64 a0 = a01.x, a1 = a01.y, a2 = a23.x, a3 = a23.y;

        // issue next k's loads BEFORE this k's FMA block (latency hiding)
        if (k < 14) {
            a01 = *(const ulonglong2*)&As[k + 1][na];
            a23 = *(const ulonglong2*)&As[k + 1][na + 4];
            fb0 = *(const float4*)&Bs[k + 1][ma];
            fb1 = *(const float4*)&Bs[k + 1][64 + ma];
        }

        #pragma unroll
        for (int c = 0; c < 8; c++) {
            fma2(acc[0][c], a0, b[c]);
            fma2(acc[1][c], a1, b[c]);
            fma2(acc[2][c], a2, b[c]);
            fma2(acc[3][c], a3, b[c]);
        }
    }

    // ---- store: 8 rows x two coalesced float4 ----
    float* o = out + (size_t)batch * NN * NN + (size_t)n0 * NN + m0;
    #pragma unroll
    for (int p = 0; p < 4; p++) {
        float2 u[8];
        #pragma unroll
        for (int c = 0; c < 8; c++) u[c] = unpack2(acc[p][c]);
        float* row0 = o + (size_t)(na + 2 * p) * NN;
        float* row1 = o + (size_t)(na + 2 * p + 1) * NN;
        __stcs((float4*)(row0 + ma),      make_float4(u[0].x, u[1].x, u[2].x, u[3].x));
        __stcs((float4*)(row0 + 64 + ma), make_float4(u[4].x, u[5].x, u[6].x, u[7].x));
        __stcs((float4*)(row1 + ma),      make_float4(u[0].y, u[1].y, u[2].y, u[3].y));
        __stcs((float4*)(row1 + 64 + ma), make_float4(u[4].y, u[5].y, u[6].y, u[7].y));
    }
}

// ---------------------------------------------------------------------------
extern "C" void kernel_launch(void* const* d_in, const int* in_sizes, int n_in,
                              void* d_out, int out_size)
{
    const float* q  = (const float*)d_in[0];
    const float* k  = (const float*)d_in[1];
    const float* rq = (const float*)d_in[2];
    const float* rk = (const float*)d_in[3];
    float* out = (float*)d_out;

    int blocks = (2 * NROWS + 255) / 256;
    sh_expand_kernel<<<blocks, 256>>>(q, k, rq, rk);

    dim3 grid(NN / 128, NN / 128, NBATCH);  // 8 x 8 x 128
    score_gemm_kernel<<<grid, 256>>>(out);
}

// round 6
// speedup vs baseline: 1.1927x; 1.0003x over previous
#include <cuda_runtime.h>
#include <math.h>

// Problem dims (fixed by the reference setup_inputs)
#define BB   2
#define NN   1024
#define HG   64            // H*G
#define NBATCH (BB*HG)     // 128 independent GEMM batches
#define NROWS  (BB*NN*HG)  // 131072 SH rows per side
#define DPAD 16            // 15 SH components padded to 16 for float4

// Scratch: Y_q / Y_k in [B, H, G, N, 16] layout (batch-major, row n, padded d)
__device__ float g_Yq[(size_t)NBATCH * NN * DPAD];
__device__ float g_Yk[(size_t)NBATCH * NN * DPAD];

typedef unsigned long long u64;

// ---------------------------------------------------------------------------
// packed f32x2 helpers (Blackwell FFMA2 — only reachable via PTX)
// ---------------------------------------------------------------------------
__device__ __forceinline__ void fma2(u64& d, u64 a, u64 b)
{
    asm("fma.rn.f32x2 %0, %1, %2, %0;" : "+l"(d) : "l"(a), "l"(b));
}

__device__ __forceinline__ u64 pack_dup(float v)
{
    u64 r;
    asm("mov.b64 %0, {%1, %1};" : "=l"(r) : "f"(v));
    return r;
}

__device__ __forceinline__ float2 unpack2(u64 v)
{
    float2 r;
    asm("mov.b64 {%0, %1}, %2;" : "=f"(r.x), "=f"(r.y) : "l"(v));
    return r;
}

// ---------------------------------------------------------------------------
// Kernel 1: rotate -> normalize -> spherical harmonics for BOTH q and k.
// One thread per (side, b, n, h, g). 1/sqrt(15) folded into the q side.
// ---------------------------------------------------------------------------
__global__ void sh_expand_kernel(const float* __restrict__ q_in,
                                 const float* __restrict__ k_in,
                                 const float* __restrict__ rq_in,
                                 const float* __restrict__ rk_in)
{
    int gt = blockIdx.x * blockDim.x + threadIdx.x;
    if (gt >= 2 * NROWS) return;
    int which = gt >= NROWS;          // 0 -> q, 1 -> k
    int t = gt - which * NROWS;

    const float* v_in = which ? k_in : q_in;
    const float* r_in = which ? rk_in : rq_in;
    float scale = which ? 1.0f : 0.2581988897471611f;  // 1/sqrt(15)

    int hg = t & (HG - 1);       // h*G + g
    int bn = t >> 6;             // b*N + n
    int b  = bn >> 10;           // /N
    int n  = bn & (NN - 1);

    const float* q = v_in + (size_t)t * 3;
    const float* r = r_in + (size_t)bn * 9;
    float q0 = q[0], q1 = q[1], q2 = q[2];

    float vx = r[0]*q0 + r[1]*q1 + r[2]*q2;
    float vy = r[3]*q0 + r[4]*q1 + r[5]*q2;
    float vz = r[6]*q0 + r[7]*q1 + r[8]*q2;

    float nrm = sqrtf(vx*vx + vy*vy + vz*vz);
    float inv = 1.0f / fmaxf(nrm, 1e-12f);
    float x = vx*inv, y = vy*inv, z = vz*inv;
    float x2 = x*x, y2 = y*y, z2 = z*z;

    const float f1 = 0.4886025119029199f * scale;  // sqrt(3/(4pi))
    const float f2 = 0.6307831305050401f * scale;  // sqrt(5/(4pi))
    const float f3 = 0.7463526651802308f * scale;  // sqrt(7/(4pi))
    const float s3  = 1.7320508075688772f;
    const float s15 = 3.8729833462074170f;
    const float c1  = 0.6123724356957945f;         // sqrt(3/8)
    const float c3  = 0.7905694150420949f;         // sqrt(5/8)

    float Y0  = f1 * x;
    float Y1  = f1 * y;
    float Y2  = f1 * z;

    float Y3  = f2 * (s3 * x * z);
    float Y4  = f2 * (s3 * x * y);
    float Y5  = f2 * (y2 - 0.5f * (x2 + z2));
    float Y6  = f2 * (s3 * y * z);
    float Y7  = f2 * (0.5f * s3) * (z2 - x2);

    float Y8  = f3 * (c3 * x * (3.0f * z2 - x2));
    float Y9  = f3 * (s15 * x * y * z);
    float Y10 = f3 * (c1 * x * (4.0f * y2 - x2 - z2));
    float Y11 = f3 * (0.5f * y * (2.0f * y2 - 3.0f * x2 - 3.0f * z2));
    float Y12 = f3 * (c1 * z * (4.0f * y2 - x2 - z2));
    float Y13 = f3 * (0.5f * s15) * (y * (z2 - x2));
    float Y14 = f3 * (c3 * z * (z2 - 3.0f * x2));

    float* Y = which ? g_Yk : g_Yq;
    size_t obase = (((size_t)b * HG + hg) * NN + n) * DPAD;
    float4* o = (float4*)(Y + obase);
    o[0] = make_float4(Y0,  Y1,  Y2,  Y3);
    o[1] = make_float4(Y4,  Y5,  Y6,  Y7);
    o[2] = make_float4(Y8,  Y9,  Y10, Y11);
    o[3] = make_float4(Y12, Y13, Y14, 0.0f);
}

// ---------------------------------------------------------------------------
// Kernel 2: strip-persistent batched small-K GEMM with packed f32x2 FMA.
// scores[batch, n, m] = sum_d Yq[n,d] * Yk[m,d]
// Each block owns a 128(n) x 512(m) strip: A staged once, 4 B-tiles of
// 128 cols double-buffered in smem with register prefetch (LDG for tile j+1
// issued before tile j's compute, STS + one sync per tile).
// Inner loop: 8x8 micro-tile, acc packed over row pairs, 1.0 lane-B/FMA.
// ---------------------------------------------------------------------------
__global__ void __launch_bounds__(256, 2) score_gemm_kernel(float* __restrict__ out)
{
    __shared__ __align__(16) float As[15][128];      // [k][n]
    __shared__ __align__(16) float Bs[2][15][128];   // [buf][k][m]

    int batch = blockIdx.z;
    int n0 = blockIdx.y * 128;
    int ms = blockIdx.x * 512;        // strip base in m
    int tid = threadIdx.x;

    const float4* A4 = (const float4*)(g_Yq + (size_t)batch * NN * DPAD);
    const float4* B4 = (const float4*)(g_Yk + (size_t)batch * NN * DPAD);

    int srow = tid >> 2;              // 0..63
    int sc   = tid & 3;               // k-chunk
    int skb  = sc * 4;

    // ---- prologue: stage A (128 rows) and B tile 0 ----
    #pragma unroll
    for (int i = 0; i < 2; i++) {
        int row = srow + i * 64;
        float4 va = A4[(size_t)(n0 + row) * 4 + sc];
        float4 vb = B4[(size_t)(ms + row) * 4 + sc];
        As[skb + 0][row] = va.x;
        As[skb + 1][row] = va.y;
        As[skb + 2][row] = va.z;
        if (skb + 3 < 15) As[skb + 3][row] = va.w;
        Bs[0][skb + 0][row] = vb.x;
        Bs[0][skb + 1][row] = vb.y;
        Bs[0][skb + 2][row] = vb.z;
        if (skb + 3 < 15) Bs[0][skb + 3][row] = vb.w;
    }
    __syncthreads();

    int tx = tid & 15;           // m micro-tile
    int ty = tid >> 4;           // n micro-tile (0..15)
    int na = ty * 8;             // rows na..na+7 (consecutive)
    int ma = tx * 4;             // cols ma..ma+3 and 64+ma..64+ma+3

    #pragma unroll 1
    for (int j = 0; j < 4; j++) {
        int buf = j & 1;
        const float (*Bsb)[128] = Bs[buf];

        // prefetch next B tile into registers (hidden by compute below)
        float4 p0, p1;
        if (j < 3) {
            size_t base = (size_t)(ms + (j + 1) * 128);
            p0 = B4[(base + srow) * 4 + sc];
            p1 = B4[(base + srow + 64) * 4 + sc];
        }

        // ---- compute 128x128 tile from As x Bsb ----
        u64 acc[4][8];
        #pragma unroll
        for (int p = 0; p < 4; p++)
            #pragma unroll
            for (int c = 0; c < 8; c++) acc[p][c] = 0ull;

        ulonglong2 a01 = *(const ulonglong2*)&As[0][na];
        ulonglong2 a23 = *(const ulonglong2*)&As[0][na + 4];
        float4 fb0 = *(const float4*)&Bsb[0][ma];
        float4 fb1 = *(const float4*)&Bsb[0][64 + ma];

        #pragma unroll
        for (int k = 0; k < 15; k++) {
            u64 b[8];
            b[0] = pack_dup(fb0.x); b[1] = pack_dup(fb0.y);
            b[2] = pack_dup(fb0.z); b[3] = pack_dup(fb0.w);
            b[4] = pack_dup(fb1.x); b[5] = pack_dup(fb1.y);
            b[6] = pack_dup(fb1.z); b[7] = pack_dup(fb1.w);

            u64 a0 = a01.x, a1 = a01.y, a2 = a23.x, a3 = a23.y;

            if (k < 14) {
                a01 = *(const ulonglong2*)&As[k + 1][na];
                a23 = *(const ulonglong2*)&As[k + 1][na + 4];
                fb0 = *(const float4*)&Bsb[k + 1][ma];
                fb1 = *(const float4*)&Bsb[k + 1][64 + ma];
            }

            #pragma unroll
            for (int c = 0; c < 8; c++) {
                fma2(acc[0][c], a0, b[c]);
                fma2(acc[1][c], a1, b[c]);
                fma2(acc[2][c], a2, b[c]);
                fma2(acc[3][c], a3, b[c]);
            }
        }

        // ---- store tile j: 8 rows x two coalesced float4 ----
        float* o = out + (size_t)batch * NN * NN + (size_t)n0 * NN
                       + (size_t)(ms + j * 128);
        #pragma unroll
        for (int p = 0; p < 4; p++) {
            float2 u[8];
            #pragma unroll
            for (int c = 0; c < 8; c++) u[c] = unpack2(acc[p][c]);
            float* row0 = o + (size_t)(na + 2 * p) * NN;
            float* row1 = o + (size_t)(na + 2 * p + 1) * NN;
            __stcs((float4*)(row0 + ma),      make_float4(u[0].x, u[1].x, u[2].x, u[3].x));
            __stcs((float4*)(row0 + 64 + ma), make_float4(u[4].x, u[5].x, u[6].x, u[7].x));
            __stcs((float4*)(row1 + ma),      make_float4(u[0].y, u[1].y, u[2].y, u[3].y));
            __stcs((float4*)(row1 + 64 + ma), make_float4(u[4].y, u[5].y, u[6].y, u[7].y));
        }

        // ---- publish prefetched tile into the other buffer ----
        if (j < 3) {
            float (*Bn)[128] = Bs[buf ^ 1];
            // all threads finished reading Bs[buf^1] at iter j-1; the sync at
            // the end of iter j-1 ordered those reads before these writes.
            Bn[skb + 0][srow] = p0.x;
            Bn[skb + 1][srow] = p0.y;
            Bn[skb + 2][srow] = p0.z;
            if (skb + 3 < 15) Bn[skb + 3][srow] = p0.w;
            Bn[skb + 0][srow + 64] = p1.x;
            Bn[skb + 1][srow + 64] = p1.y;
            Bn[skb + 2][srow + 64] = p1.z;
            if (skb + 3 < 15) Bn[skb + 3][srow + 64] = p1.w;
            __syncthreads();
        }
    }
}

// ---------------------------------------------------------------------------
extern "C" void kernel_launch(void* const* d_in, const int* in_sizes, int n_in,
                              void* d_out, int out_size)
{
    const float* q  = (const float*)d_in[0];
    const float* k  = (const float*)d_in[1];
    const float* rq = (const float*)d_in[2];
    const float* rk = (const float*)d_in[3];
    float* out = (float*)d_out;

    int blocks = (2 * NROWS + 255) / 256;
    sh_expand_kernel<<<blocks, 256>>>(q, k, rq, rk);

    dim3 grid(NN / 512, NN / 128, NBATCH);  // 2 x 8 x 128 = 2048 blocks
    score_gemm_kernel<<<grid, 256>>>(out);
}